// round 11
// baseline (speedup 1.0000x reference)
#include <cuda_runtime.h>
#include <cuda_fp16.h>
#include <cstdint>
#include <cstddef>

// W8A16 GEMM, legacy-HMMA path (harness targets plain sm_103: tcgen05 unavailable).
// Contract (confirmed R4): X f32[M,K] (fp16-valued), W int32[N,K] (int8-valued),
// scale/bias f32[N], out f32[M,N] (fp16-rounded values).
// R11 = R10 with the B-fragment swizzle carry bug fixed (XOR the composed
// offset, never add after XOR). W kept int8 end-to-end: cvt_w bakes the mma
// B-fragment permutation into each 16-k group; mainloop dequantizes in-register
// (XOR+PRMT+sub.f16x2, exact). Stage = A 16KB + B 8KB -> 4-stage cp.async ring
// (wait_group 2), 128x128 CTA, 8 warps (32x64 warp tiles), 2 CTAs/SM.

namespace {

constexpr int MM = 8192, KK = 4096, NN = 11008;
constexpr int BM = 128, BN = 128, BK = 64;
constexpr int THREADS = 256;
constexpr int STAGES = 4;
constexpr int ASTAGE = BM * 128;    // 16 KB (fp16, 128B rows)
constexpr int BSTAGE = BN * 64;     // 8 KB  (int8, 64B rows)
constexpr int SMEM_TOTAL = STAGES * (ASTAGE + BSTAGE);  // 96 KB

__device__ __align__(256) __half  g_X16[(size_t)MM * KK];  // 64 MB
__device__ __align__(256) int8_t  g_W8 [(size_t)NN * KK];  // 45 MB

// ---------------- converters ----------------
__global__ void __launch_bounds__(256) cvt_x(const float* __restrict__ x, int total8) {
    int t = blockIdx.x * blockDim.x + threadIdx.x;
    if (t >= total8) return;
    size_t base = (size_t)t * 8;
    const float4* p = (const float4*)(x + base);
    float4 a = p[0], b = p[1];
    __half2 h0 = __floats2half2_rn(a.x, a.y), h1 = __floats2half2_rn(a.z, a.w);
    __half2 h2 = __floats2half2_rn(b.x, b.y), h3 = __floats2half2_rn(b.z, b.w);
    uint4 o;
    o.x = *(uint32_t*)&h0; o.y = *(uint32_t*)&h1;
    o.z = *(uint32_t*)&h2; o.w = *(uint32_t*)&h3;
    *(uint4*)(g_X16 + base) = o;
}

// W int32 -> int8, with per-16k permutation so that ldmatrix-as-b16 + in-reg
// convert reproduces the exact mma.sync B fragment layout:
//   stored word c (bytes 4c..4c+3) = k values {2c, 2c+1, 2c+8, 2c+9}, c=0..3.
__global__ void __launch_bounds__(256) cvt_w(const int* __restrict__ w, int total16) {
    int t = blockIdx.x * blockDim.x + threadIdx.x;
    if (t >= total16) return;
    size_t base = (size_t)t * 16;
    int v[16];
    const int4* p = (const int4*)(w + base);
#pragma unroll
    for (int i = 0; i < 4; i++) {
        int4 q = p[i];
        v[4 * i] = q.x; v[4 * i + 1] = q.y; v[4 * i + 2] = q.z; v[4 * i + 3] = q.w;
    }
    uint4 o;
    uint32_t wds[4];
#pragma unroll
    for (int c = 0; c < 4; c++) {
        wds[c] = (uint32_t)(v[2 * c] & 0xFF)
               | ((uint32_t)(v[2 * c + 1] & 0xFF) << 8)
               | ((uint32_t)(v[2 * c + 8] & 0xFF) << 16)
               | ((uint32_t)(v[2 * c + 9] & 0xFF) << 24);
    }
    o.x = wds[0]; o.y = wds[1]; o.z = wds[2]; o.w = wds[3];
    *(uint4*)(g_W8 + base) = o;
}

// ---------------- helpers ----------------
__device__ __forceinline__ uint32_t swz128(uint32_t x) { return x ^ ((x >> 3) & 0x70); }
__device__ __forceinline__ uint32_t swz64 (uint32_t x) { return x ^ ((x >> 3) & 0x30); }

__device__ __forceinline__ void cp_async16(uint32_t dst, const void* src) {
    asm volatile("cp.async.cg.shared.global [%0], [%1], 16;\n" :: "r"(dst), "l"(src));
}
__device__ __forceinline__ void cp_commit() { asm volatile("cp.async.commit_group;\n"); }
template <int N>
__device__ __forceinline__ void cp_wait() {
    asm volatile("cp.async.wait_group %0;\n" :: "n"(N) : "memory");
}

__device__ __forceinline__ void ldsm4(uint32_t r[4], uint32_t addr) {
    asm volatile("ldmatrix.sync.aligned.m8n8.x4.shared.b16 {%0,%1,%2,%3}, [%4];\n"
                 : "=r"(r[0]), "=r"(r[1]), "=r"(r[2]), "=r"(r[3]) : "r"(addr));
}
__device__ __forceinline__ void ldsm2(uint32_t& r0, uint32_t& r1, uint32_t addr) {
    asm volatile("ldmatrix.sync.aligned.m8n8.x2.shared.b16 {%0,%1}, [%2];\n"
                 : "=r"(r0), "=r"(r1) : "r"(addr));
}

__device__ __forceinline__ void mma16816(float c[4], const uint32_t a[4],
                                         uint32_t b0, uint32_t b1) {
    asm volatile("mma.sync.aligned.m16n8k16.row.col.f32.f16.f16.f32 "
                 "{%0,%1,%2,%3}, {%4,%5,%6,%7}, {%8,%9}, {%0,%1,%2,%3};\n"
                 : "+f"(c[0]), "+f"(c[1]), "+f"(c[2]), "+f"(c[3])
                 : "r"(a[0]), "r"(a[1]), "r"(a[2]), "r"(a[3]), "r"(b0), "r"(b1));
}

// 4 int8 (packed) -> 2 fp16x2 regs: fp16(0x6400|(v^0x80)) - 1152 = v (exact).
__device__ __forceinline__ void cvt_i8x4(uint32_t b, uint32_t& lo, uint32_t& hi) {
    uint32_t u = b ^ 0x80808080u;
    uint32_t p0 = __byte_perm(u, 0x64646464u, 0x4140);
    uint32_t p1 = __byte_perm(u, 0x64646464u, 0x4342);
    asm("sub.f16x2 %0, %1, %2;\n" : "=r"(lo) : "r"(p0), "r"(0x64806480u));
    asm("sub.f16x2 %0, %1, %2;\n" : "=r"(hi) : "r"(p1), "r"(0x64806480u));
}

__device__ __forceinline__ float rf16(float v) {
    return __half2float(__float2half_rn(v));
}

// ---------------- GEMM ----------------
__global__ void __launch_bounds__(THREADS, 2)
gemm_kernel(const float* __restrict__ scale, const float* __restrict__ bias,
            float* __restrict__ out, int M, int N, int K)
{
    extern __shared__ __align__(1024) char smem[];
    const uint32_t sA = (uint32_t)__cvta_generic_to_shared(smem);
    const uint32_t sB = sA + STAGES * ASTAGE;

    const int tid  = threadIdx.x;
    const int lane = tid & 31;
    const int warp = tid >> 5;
    const int wm = warp & 3;   // 4 warp rows x 32 M
    const int wn = warp >> 2;  // 2 warp cols x 64 N

    const int m0 = blockIdx.y * BM;
    const int n0 = blockIdx.x * BN;   // x = N: wave shares A slab, streams W
    const int KT = K / BK;

    // A staging: 1024 x 16B chunks/stage, 4 per thread; chunk i = +32 rows.
    const int arow = tid >> 3, acol = tid & 7;
    const uint32_t a_st0 = swz128((uint32_t)(arow * 128 + acol * 16));
    const __half* const a_g0 = g_X16 + (size_t)(m0 + arow) * K + acol * 8;
    constexpr size_t AGS = (size_t)32 * KK;   // 32 rows (elements)

    // B staging: 512 x 16B chunks/stage, 2 per thread; chunk i = +64 rows.
    const int brow = tid >> 2, bcol = tid & 3;
    const uint32_t b_st0 = swz64((uint32_t)(brow * 64 + bcol * 16));
    const int8_t* const b_g0 = g_W8 + (size_t)(n0 + brow) * K + bcol * 16;
    constexpr size_t BGS = (size_t)64 * KK;   // 64 rows (bytes)

    // A ldmatrix base (SW128): compose offset first, XOR constant row term last.
    const uint32_t a_off0 = (uint32_t)((wm * 32 + (lane & 15)) * 128 + (lane >> 4) * 16);
    const uint32_t axor   = (a_off0 >> 3) & 0x70;
    // B ldmatrix base (int8, 64B rows, SW64): row = wn*64 + np*16 + (lane&15).
    // XOR term = offset bits [8:7] -> row bits [2:1], i.e. (lane&15) only:
    // constant across np/ks. Keep base UNswizzled; XOR the composed offset
    // (never add after XOR - bits [5:4] would carry).
    const uint32_t b_off0 = (uint32_t)((wn * 64 + (lane & 15)) * 64);
    const uint32_t bxor   = (b_off0 >> 3) & 0x30;

    float acc[2][8][4];
#pragma unroll
    for (int mi = 0; mi < 2; mi++)
#pragma unroll
        for (int ni = 0; ni < 8; ni++)
#pragma unroll
            for (int e = 0; e < 4; e++) acc[mi][ni][e] = 0.f;

    // prologue: stages 0..2
#pragma unroll
    for (int s = 0; s < 3; s++) {
        const size_t ko = (size_t)s * BK;
#pragma unroll
        for (int i = 0; i < 4; i++)
            cp_async16(sA + s * ASTAGE + a_st0 + i * 4096, a_g0 + ko + i * AGS);
#pragma unroll
        for (int i = 0; i < 2; i++)
            cp_async16(sB + s * BSTAGE + b_st0 + i * 4096, b_g0 + ko + i * BGS);
        cp_commit();
    }
    cp_wait<2>();          // stage 0 resident
    __syncthreads();

    for (int kt = 0; kt < KT; ++kt) {
        // issue loads for kt+3 into the buffer freed at the end of kt-1
        if (kt + 3 < KT) {
            const int s = (kt + 3) % STAGES;
            const size_t ko = (size_t)(kt + 3) * BK;
#pragma unroll
            for (int i = 0; i < 4; i++)
                cp_async16(sA + s * ASTAGE + a_st0 + i * 4096, a_g0 + ko + i * AGS);
#pragma unroll
            for (int i = 0; i < 2; i++)
                cp_async16(sB + s * BSTAGE + b_st0 + i * 4096, b_g0 + ko + i * BGS);
            cp_commit();
        }

        // compute stage kt
        const uint32_t Abase = sA + (kt % STAGES) * ASTAGE;
        const uint32_t Bbase = sB + (kt % STAGES) * BSTAGE;
#pragma unroll
        for (int ks = 0; ks < 4; ++ks) {
            uint32_t a[2][4];
#pragma unroll
            for (int mi = 0; mi < 2; mi++)
                ldsm4(a[mi], Abase + ((a_off0 + mi * 2048 + ks * 32) ^ axor));
#pragma unroll
            for (int np = 0; np < 4; np++) {
                uint32_t u0, u1;                 // packed int8: rows n0-7 / n8-15
                ldsm2(u0, u1, Bbase + ((b_off0 + np * 1024 + ks * 16) ^ bxor));
                uint32_t b0, b1, b2, b3;
                cvt_i8x4(u0, b0, b1);            // (2c,2c+1) & (2c+8,2c+9): k0-15
                cvt_i8x4(u1, b2, b3);
#pragma unroll
                for (int mi = 0; mi < 2; mi++) {
                    mma16816(acc[mi][2 * np],     a[mi], b0, b1);
                    mma16816(acc[mi][2 * np + 1], a[mi], b2, b3);
                }
            }
        }

        // ensure stage kt+1 resident before next iteration
        if (kt + 1 < KT) {
            if      (kt + 3 < KT) cp_wait<2>();
            else if (kt + 2 < KT) cp_wait<1>();
            else                  cp_wait<0>();
            __syncthreads();
        }
    }

    // epilogue: scale + bias, round through fp16, f32 out
    const int gi = lane >> 2;
    const int tl = lane & 3;
#pragma unroll
    for (int ni = 0; ni < 8; ni++) {
        const int n = n0 + wn * 64 + ni * 8 + tl * 2;
        const float s0 = __ldg(scale + n), s1 = __ldg(scale + n + 1);
        const float z0 = __ldg(bias + n),  z1 = __ldg(bias + n + 1);
#pragma unroll
        for (int mi = 0; mi < 2; mi++) {
            const size_t r0 = (size_t)(m0 + wm * 32 + mi * 16 + gi);
            *(float2*)(out + r0 * N + n) =
                make_float2(rf16(acc[mi][ni][0] * s0 + z0), rf16(acc[mi][ni][1] * s1 + z1));
            *(float2*)(out + (r0 + 8) * N + n) =
                make_float2(rf16(acc[mi][ni][2] * s0 + z0), rf16(acc[mi][ni][3] * s1 + z1));
        }
    }
}

struct ForceLoad {
    ForceLoad() {
        cudaFuncAttributes a;
        cudaFuncGetAttributes(&a, (const void*)cvt_x);
        cudaFuncGetAttributes(&a, (const void*)cvt_w);
        cudaFuncGetAttributes(&a, (const void*)gemm_kernel);
        cudaFuncSetAttribute((const void*)gemm_kernel,
                             cudaFuncAttributeMaxDynamicSharedMemorySize, SMEM_TOTAL);
    }
};
ForceLoad g_forceload;

} // namespace

extern "C" void kernel_launch(void* const* d_in, const int* in_sizes, int n_in,
                              void* d_out, int out_size) {
    const float* X     = (const float*)d_in[0];
    const int*   W     = (const int*)d_in[1];
    const float* scale = (const float*)d_in[2];
    const float* bias  = (const float*)d_in[3];
    float* out = (float*)d_out;

    const int n0 = in_sizes[0];
    const int n1 = in_sizes[1];
    const int N  = in_sizes[2];            // 11008
    const int K  = n1 / N;                 // 4096
    const int M  = n0 / K;                 // 8192

    cvt_x<<<(n0 / 8 + 255) / 256, 256>>>(X, n0 / 8);
    cvt_w<<<(n1 / 16 + 255) / 256, 256>>>(W, n1 / 16);

    cudaFuncSetAttribute((const void*)gemm_kernel,
                         cudaFuncAttributeMaxDynamicSharedMemorySize, SMEM_TOTAL);
    dim3 grid(N / BN, M / BM);             // 86 x 64
    gemm_kernel<<<grid, THREADS, SMEM_TOTAL>>>(scale, bias, out, M, N, K);
}

// round 12
// speedup vs baseline: 1.0661x; 1.0661x over previous
#include <cuda_runtime.h>
#include <cuda_fp16.h>
#include <cstdint>
#include <cstddef>

// W8A16 GEMM, legacy-HMMA path (harness targets plain sm_103: tcgen05 unavailable).
// Contract (confirmed R4): X f32[M,K] (fp16-valued), W int32[N,K] (int8-valued),
// scale/bias f32[N], out f32[M,N] (fp16-rounded values).
// R12 = R7 (best: 1594us) + cross-ks double-buffering of B fragments so every
// mma consumes ldsm results issued a full ks-iteration earlier. 128x128 CTA,
// BK=64, 8 warps (32x64 warp tiles), 3-stage cp.async ring (wait_group 1),
// SW128 smem, 2 CTAs/SM.

namespace {

constexpr int MM = 8192, KK = 4096, NN = 11008;
constexpr int BM = 128, BN = 128, BK = 64;
constexpr int THREADS = 256;
constexpr int STAGES = 3;
constexpr int ASTAGE = BM * 128;   // 16 KB
constexpr int BSTAGE = BN * 128;   // 16 KB
constexpr int SMEM_TOTAL = STAGES * (ASTAGE + BSTAGE);  // 96 KB

__device__ __align__(256) __half g_X16[(size_t)MM * KK];   // 64 MB
__device__ __align__(256) __half g_W16[(size_t)NN * KK];   // 90 MB

// ---------------- converters ----------------
__global__ void __launch_bounds__(256) cvt_x(const float* __restrict__ x, int total8) {
    int t = blockIdx.x * blockDim.x + threadIdx.x;
    if (t >= total8) return;
    size_t base = (size_t)t * 8;
    const float4* p = (const float4*)(x + base);
    float4 a = p[0], b = p[1];
    __half2 h0 = __floats2half2_rn(a.x, a.y), h1 = __floats2half2_rn(a.z, a.w);
    __half2 h2 = __floats2half2_rn(b.x, b.y), h3 = __floats2half2_rn(b.z, b.w);
    uint4 o;
    o.x = *(uint32_t*)&h0; o.y = *(uint32_t*)&h1;
    o.z = *(uint32_t*)&h2; o.w = *(uint32_t*)&h3;
    *(uint4*)(g_X16 + base) = o;
}

__global__ void __launch_bounds__(256) cvt_w(const int* __restrict__ w, int total8) {
    int t = blockIdx.x * blockDim.x + threadIdx.x;
    if (t >= total8) return;
    size_t base = (size_t)t * 8;
    const int4* p = (const int4*)(w + base);
    int4 a = p[0], b = p[1];
    __half h[8];
    h[0] = __int2half_rn(a.x); h[1] = __int2half_rn(a.y);
    h[2] = __int2half_rn(a.z); h[3] = __int2half_rn(a.w);
    h[4] = __int2half_rn(b.x); h[5] = __int2half_rn(b.y);
    h[6] = __int2half_rn(b.z); h[7] = __int2half_rn(b.w);
    uint4 o;
    o.x = *(uint32_t*)&h[0]; o.y = *(uint32_t*)&h[2];
    o.z = *(uint32_t*)&h[4]; o.w = *(uint32_t*)&h[6];
    *(uint4*)(g_W16 + base) = o;
}

// ---------------- helpers ----------------
__device__ __forceinline__ uint32_t swz(uint32_t x) { return x ^ ((x >> 3) & 0x70); }

__device__ __forceinline__ void cp_async16(uint32_t dst, const void* src) {
    asm volatile("cp.async.cg.shared.global [%0], [%1], 16;\n" :: "r"(dst), "l"(src));
}
__device__ __forceinline__ void cp_commit() { asm volatile("cp.async.commit_group;\n"); }
template <int N>
__device__ __forceinline__ void cp_wait() {
    asm volatile("cp.async.wait_group %0;\n" :: "n"(N) : "memory");
}

__device__ __forceinline__ void ldsm4(uint32_t r[4], uint32_t addr) {
    asm volatile("ldmatrix.sync.aligned.m8n8.x4.shared.b16 {%0,%1,%2,%3}, [%4];\n"
                 : "=r"(r[0]), "=r"(r[1]), "=r"(r[2]), "=r"(r[3]) : "r"(addr));
}

__device__ __forceinline__ void mma16816(float c[4], const uint32_t a[4],
                                         uint32_t b0, uint32_t b1) {
    asm volatile("mma.sync.aligned.m16n8k16.row.col.f32.f16.f16.f32 "
                 "{%0,%1,%2,%3}, {%4,%5,%6,%7}, {%8,%9}, {%0,%1,%2,%3};\n"
                 : "+f"(c[0]), "+f"(c[1]), "+f"(c[2]), "+f"(c[3])
                 : "r"(a[0]), "r"(a[1]), "r"(a[2]), "r"(a[3]), "r"(b0), "r"(b1));
}

__device__ __forceinline__ float rf16(float v) {
    return __half2float(__float2half_rn(v));
}

// ---------------- GEMM ----------------
__global__ void __launch_bounds__(THREADS, 2)
gemm_kernel(const float* __restrict__ scale, const float* __restrict__ bias,
            float* __restrict__ out, int M, int N, int K)
{
    extern __shared__ __align__(1024) char smem[];
    const uint32_t sA = (uint32_t)__cvta_generic_to_shared(smem);
    const uint32_t sB = sA + STAGES * ASTAGE;

    const int tid  = threadIdx.x;
    const int lane = tid & 31;
    const int warp = tid >> 5;
    const int wm = warp & 3;   // 4 warp rows x 32 M
    const int wn = warp >> 2;  // 2 warp cols x 64 N

    const int m0 = blockIdx.y * BM;
    const int n0 = blockIdx.x * BN;   // x = N: a wave shares the A slab, streams W
    const int KT = K / BK;

    // staging: 1024 x 16B chunks per operand stage, 4 per thread
    uint32_t a_st[4]; const __half* a_g[4]; const __half* b_g[4];
#pragma unroll
    for (int i = 0; i < 4; i++) {
        int chunk = tid + i * THREADS;
        int row = chunk >> 3, c = chunk & 7;
        a_st[i] = swz((uint32_t)(row * 128 + c * 16));
        a_g[i]  = g_X16 + (size_t)(m0 + row) * K + c * 8;
        b_g[i]  = g_W16 + (size_t)(n0 + row) * K + c * 8;
    }

    // ldmatrix base offsets (swizzle xor is row-only -> constant per thread)
    const uint32_t a_off0 = (uint32_t)((wm * 32 + (lane & 15)) * 128 + (lane >> 4) * 16);
    const uint32_t axor   = (a_off0 >> 3) & 0x70;
    const uint32_t b_off0 = (uint32_t)((wn * 64 + ((lane >> 4) & 1) * 8 + (lane & 7)) * 128
                                       + ((lane >> 3) & 1) * 16);
    const uint32_t bxor   = (b_off0 >> 3) & 0x70;

    float acc[2][8][4];
#pragma unroll
    for (int mi = 0; mi < 2; mi++)
#pragma unroll
        for (int ni = 0; ni < 8; ni++)
#pragma unroll
            for (int e = 0; e < 4; e++) acc[mi][ni][e] = 0.f;

    // prologue: stages 0 and 1
#pragma unroll
    for (int s = 0; s < 2; s++) {
        const size_t ko = (size_t)s * BK;
#pragma unroll
        for (int i = 0; i < 4; i++) cp_async16(sA + s * ASTAGE + a_st[i], a_g[i] + ko);
#pragma unroll
        for (int i = 0; i < 4; i++) cp_async16(sB + s * BSTAGE + a_st[i], b_g[i] + ko);
        cp_commit();
    }
    cp_wait<1>();          // stage 0 resident
    __syncthreads();

    for (int kt = 0; kt < KT; ++kt) {
        // issue loads for kt+2 into the buffer freed at the end of kt-1
        if (kt + 2 < KT) {
            const int s = (kt + 2) % STAGES;
            const size_t ko = (size_t)(kt + 2) * BK;
#pragma unroll
            for (int i = 0; i < 4; i++) cp_async16(sA + s * ASTAGE + a_st[i], a_g[i] + ko);
#pragma unroll
            for (int i = 0; i < 4; i++) cp_async16(sB + s * BSTAGE + a_st[i], b_g[i] + ko);
            cp_commit();
        }

        // compute stage kt with B fragments double-buffered across ks
        const uint32_t Abase = sA + (kt % STAGES) * ASTAGE;
        const uint32_t Bbase = sB + (kt % STAGES) * BSTAGE;

        uint32_t bfr[2][4][4];     // [buf][np][reg]
#pragma unroll
        for (int np = 0; np < 4; np++)
            ldsm4(bfr[0][np], Bbase + ((b_off0 + np * 2048) ^ bxor));

#pragma unroll
        for (int ks = 0; ks < 4; ++ks) {
            const int cur = ks & 1, nxt = cur ^ 1;
            uint32_t a[2][4];
#pragma unroll
            for (int mi = 0; mi < 2; mi++)
                ldsm4(a[mi], Abase + ((a_off0 + mi * 2048 + ks * 32) ^ axor));
            if (ks < 3) {
#pragma unroll
                for (int np = 0; np < 4; np++)
                    ldsm4(bfr[nxt][np], Bbase + ((b_off0 + np * 2048 + (ks + 1) * 32) ^ bxor));
            }
#pragma unroll
            for (int np = 0; np < 4; np++)
#pragma unroll
                for (int mi = 0; mi < 2; mi++) {
                    mma16816(acc[mi][2 * np],     a[mi], bfr[cur][np][0], bfr[cur][np][1]);
                    mma16816(acc[mi][2 * np + 1], a[mi], bfr[cur][np][2], bfr[cur][np][3]);
                }
        }

        // ensure stage kt+1 resident before next iteration
        if (kt + 1 < KT) {
            if (kt + 2 < KT) cp_wait<1>(); else cp_wait<0>();
            __syncthreads();
        }
    }

    // epilogue: scale + bias, round through fp16, f32 out
    const int gi = lane >> 2;
    const int tl = lane & 3;
#pragma unroll
    for (int ni = 0; ni < 8; ni++) {
        const int n = n0 + wn * 64 + ni * 8 + tl * 2;
        const float s0 = __ldg(scale + n), s1 = __ldg(scale + n + 1);
        const float z0 = __ldg(bias + n),  z1 = __ldg(bias + n + 1);
#pragma unroll
        for (int mi = 0; mi < 2; mi++) {
            const size_t r0 = (size_t)(m0 + wm * 32 + mi * 16 + gi);
            *(float2*)(out + r0 * N + n) =
                make_float2(rf16(acc[mi][ni][0] * s0 + z0), rf16(acc[mi][ni][1] * s1 + z1));
            *(float2*)(out + (r0 + 8) * N + n) =
                make_float2(rf16(acc[mi][ni][2] * s0 + z0), rf16(acc[mi][ni][3] * s1 + z1));
        }
    }
}

struct ForceLoad {
    ForceLoad() {
        cudaFuncAttributes a;
        cudaFuncGetAttributes(&a, (const void*)cvt_x);
        cudaFuncGetAttributes(&a, (const void*)cvt_w);
        cudaFuncGetAttributes(&a, (const void*)gemm_kernel);
        cudaFuncSetAttribute((const void*)gemm_kernel,
                             cudaFuncAttributeMaxDynamicSharedMemorySize, SMEM_TOTAL);
    }
};
ForceLoad g_forceload;

} // namespace

extern "C" void kernel_launch(void* const* d_in, const int* in_sizes, int n_in,
                              void* d_out, int out_size) {
    const float* X     = (const float*)d_in[0];
    const int*   W     = (const int*)d_in[1];
    const float* scale = (const float*)d_in[2];
    const float* bias  = (const float*)d_in[3];
    float* out = (float*)d_out;

    const int n0 = in_sizes[0];
    const int n1 = in_sizes[1];
    const int N  = in_sizes[2];            // 11008
    const int K  = n1 / N;                 // 4096
    const int M  = n0 / K;                 // 8192

    cvt_x<<<(n0 / 8 + 255) / 256, 256>>>(X, n0 / 8);
    cvt_w<<<(n1 / 8 + 255) / 256, 256>>>(W, n1 / 8);

    cudaFuncSetAttribute((const void*)gemm_kernel,
                         cudaFuncAttributeMaxDynamicSharedMemorySize, SMEM_TOTAL);
    dim3 grid(N / BN, M / BM);             // 86 x 64
    gemm_kernel<<<grid, THREADS, SMEM_TOTAL>>>(scale, bias, out, M, N, K);
}

// round 13
// speedup vs baseline: 1.0860x; 1.0186x over previous
#include <cuda_runtime.h>
#include <cuda_fp16.h>
#include <cstdint>
#include <cstddef>

// W8A16 GEMM, legacy-HMMA path (harness targets plain sm_103: tcgen05 unavailable).
// Contract (confirmed R4): X f32[M,K] (fp16-valued), W int32[N,K] (int8-valued),
// scale/bias f32[N], out f32[M,N] (fp16-rounded values).
// R13 = R7 (best: 1594us, untouched mainloop) + grouped CTA rasterization
// (GROUP_M=32 supertiles): a wave works on 32 M-tiles x ~9 N-tiles so the
// W + A working set (~41MB) stays L2-resident, cutting DRAM traffic ~5x.
// 128x128 CTA, BK=64, 8 warps (32x64 warp tiles), 3-stage cp.async ring
// (wait_group 1), SW128 smem, ldmatrix + mma.sync, 2 CTAs/SM.

namespace {

constexpr int MM = 8192, KK = 4096, NN = 11008;
constexpr int BM = 128, BN = 128, BK = 64;
constexpr int THREADS = 256;
constexpr int STAGES = 3;
constexpr int GROUP_M = 32;        // M-tiles per raster group (64 % 32 == 0)
constexpr int ASTAGE = BM * 128;   // 16 KB
constexpr int BSTAGE = BN * 128;   // 16 KB
constexpr int SMEM_TOTAL = STAGES * (ASTAGE + BSTAGE);  // 96 KB

__device__ __align__(256) __half g_X16[(size_t)MM * KK];   // 64 MB
__device__ __align__(256) __half g_W16[(size_t)NN * KK];   // 90 MB

// ---------------- converters ----------------
__global__ void __launch_bounds__(256) cvt_x(const float* __restrict__ x, int total8) {
    int t = blockIdx.x * blockDim.x + threadIdx.x;
    if (t >= total8) return;
    size_t base = (size_t)t * 8;
    const float4* p = (const float4*)(x + base);
    float4 a = p[0], b = p[1];
    __half2 h0 = __floats2half2_rn(a.x, a.y), h1 = __floats2half2_rn(a.z, a.w);
    __half2 h2 = __floats2half2_rn(b.x, b.y), h3 = __floats2half2_rn(b.z, b.w);
    uint4 o;
    o.x = *(uint32_t*)&h0; o.y = *(uint32_t*)&h1;
    o.z = *(uint32_t*)&h2; o.w = *(uint32_t*)&h3;
    *(uint4*)(g_X16 + base) = o;
}

__global__ void __launch_bounds__(256) cvt_w(const int* __restrict__ w, int total8) {
    int t = blockIdx.x * blockDim.x + threadIdx.x;
    if (t >= total8) return;
    size_t base = (size_t)t * 8;
    const int4* p = (const int4*)(w + base);
    int4 a = p[0], b = p[1];
    __half h[8];
    h[0] = __int2half_rn(a.x); h[1] = __int2half_rn(a.y);
    h[2] = __int2half_rn(a.z); h[3] = __int2half_rn(a.w);
    h[4] = __int2half_rn(b.x); h[5] = __int2half_rn(b.y);
    h[6] = __int2half_rn(b.z); h[7] = __int2half_rn(b.w);
    uint4 o;
    o.x = *(uint32_t*)&h[0]; o.y = *(uint32_t*)&h[2];
    o.z = *(uint32_t*)&h[4]; o.w = *(uint32_t*)&h[6];
    *(uint4*)(g_W16 + base) = o;
}

// ---------------- helpers ----------------
__device__ __forceinline__ uint32_t swz(uint32_t x) { return x ^ ((x >> 3) & 0x70); }

__device__ __forceinline__ void cp_async16(uint32_t dst, const void* src) {
    asm volatile("cp.async.cg.shared.global [%0], [%1], 16;\n" :: "r"(dst), "l"(src));
}
__device__ __forceinline__ void cp_commit() { asm volatile("cp.async.commit_group;\n"); }
template <int N>
__device__ __forceinline__ void cp_wait() {
    asm volatile("cp.async.wait_group %0;\n" :: "n"(N) : "memory");
}

__device__ __forceinline__ void ldsm4(uint32_t r[4], uint32_t addr) {
    asm volatile("ldmatrix.sync.aligned.m8n8.x4.shared.b16 {%0,%1,%2,%3}, [%4];\n"
                 : "=r"(r[0]), "=r"(r[1]), "=r"(r[2]), "=r"(r[3]) : "r"(addr));
}

__device__ __forceinline__ void mma16816(float c[4], const uint32_t a[4],
                                         uint32_t b0, uint32_t b1) {
    asm volatile("mma.sync.aligned.m16n8k16.row.col.f32.f16.f16.f32 "
                 "{%0,%1,%2,%3}, {%4,%5,%6,%7}, {%8,%9}, {%0,%1,%2,%3};\n"
                 : "+f"(c[0]), "+f"(c[1]), "+f"(c[2]), "+f"(c[3])
                 : "r"(a[0]), "r"(a[1]), "r"(a[2]), "r"(a[3]), "r"(b0), "r"(b1));
}

__device__ __forceinline__ float rf16(float v) {
    return __half2float(__float2half_rn(v));
}

// ---------------- GEMM ----------------
__global__ void __launch_bounds__(THREADS, 2)
gemm_kernel(const float* __restrict__ scale, const float* __restrict__ bias,
            float* __restrict__ out, int M, int N, int K)
{
    extern __shared__ __align__(1024) char smem[];
    const uint32_t sA = (uint32_t)__cvta_generic_to_shared(smem);
    const uint32_t sB = sA + STAGES * ASTAGE;

    const int tid  = threadIdx.x;
    const int lane = tid & 31;
    const int warp = tid >> 5;
    const int wm = warp & 3;   // 4 warp rows x 32 M
    const int wn = warp >> 2;  // 2 warp cols x 64 N

    // Grouped rasterization: linear id -> (m-tile, n-tile) with GROUP_M
    // consecutive m-tiles iterated fastest, so a wave's working set is
    // GROUP_M A-slabs + ~(wave/GROUP_M) W-slabs (L2-resident).
    const int lin   = blockIdx.y * gridDim.x + blockIdx.x;
    const int gsize = GROUP_M * gridDim.x;          // CTAs per group
    const int gid   = lin / gsize;
    const int rem   = lin - gid * gsize;
    const int mt    = gid * GROUP_M + (rem % GROUP_M);
    const int nt    = rem / GROUP_M;
    const int m0 = mt * BM;
    const int n0 = nt * BN;
    const int KT = K / BK;

    // staging: 1024 x 16B chunks per operand stage, 4 per thread
    uint32_t a_st[4]; const __half* a_g[4]; const __half* b_g[4];
#pragma unroll
    for (int i = 0; i < 4; i++) {
        int chunk = tid + i * THREADS;
        int row = chunk >> 3, c = chunk & 7;
        a_st[i] = swz((uint32_t)(row * 128 + c * 16));
        a_g[i]  = g_X16 + (size_t)(m0 + row) * K + c * 8;
        b_g[i]  = g_W16 + (size_t)(n0 + row) * K + c * 8;
    }

    // ldmatrix base offsets (swizzle xor is row-only -> constant per thread)
    const uint32_t a_off0 = (uint32_t)((wm * 32 + (lane & 15)) * 128 + (lane >> 4) * 16);
    const uint32_t axor   = (a_off0 >> 3) & 0x70;
    const uint32_t b_off0 = (uint32_t)((wn * 64 + ((lane >> 4) & 1) * 8 + (lane & 7)) * 128
                                       + ((lane >> 3) & 1) * 16);
    const uint32_t bxor   = (b_off0 >> 3) & 0x70;

    float acc[2][8][4];
#pragma unroll
    for (int mi = 0; mi < 2; mi++)
#pragma unroll
        for (int ni = 0; ni < 8; ni++)
#pragma unroll
            for (int e = 0; e < 4; e++) acc[mi][ni][e] = 0.f;

    // prologue: stages 0 and 1
#pragma unroll
    for (int s = 0; s < 2; s++) {
        const size_t ko = (size_t)s * BK;
#pragma unroll
        for (int i = 0; i < 4; i++) cp_async16(sA + s * ASTAGE + a_st[i], a_g[i] + ko);
#pragma unroll
        for (int i = 0; i < 4; i++) cp_async16(sB + s * BSTAGE + a_st[i], b_g[i] + ko);
        cp_commit();
    }
    cp_wait<1>();          // stage 0 resident
    __syncthreads();

    for (int kt = 0; kt < KT; ++kt) {
        // issue loads for kt+2 into the buffer freed at the end of kt-1
        if (kt + 2 < KT) {
            const int s = (kt + 2) % STAGES;
            const size_t ko = (size_t)(kt + 2) * BK;
#pragma unroll
            for (int i = 0; i < 4; i++) cp_async16(sA + s * ASTAGE + a_st[i], a_g[i] + ko);
#pragma unroll
            for (int i = 0; i < 4; i++) cp_async16(sB + s * BSTAGE + a_st[i], b_g[i] + ko);
            cp_commit();
        }

        // compute stage kt
        const uint32_t Abase = sA + (kt % STAGES) * ASTAGE;
        const uint32_t Bbase = sB + (kt % STAGES) * BSTAGE;
#pragma unroll
        for (int ks = 0; ks < 4; ++ks) {
            uint32_t a[2][4];
#pragma unroll
            for (int mi = 0; mi < 2; mi++)
                ldsm4(a[mi], Abase + ((a_off0 + mi * 2048 + ks * 32) ^ axor));
#pragma unroll
            for (int np = 0; np < 4; np++) {
                uint32_t b[4];
                ldsm4(b, Bbase + ((b_off0 + np * 2048 + ks * 32) ^ bxor));
#pragma unroll
                for (int mi = 0; mi < 2; mi++) {
                    mma16816(acc[mi][2 * np],     a[mi], b[0], b[1]);
                    mma16816(acc[mi][2 * np + 1], a[mi], b[2], b[3]);
                }
            }
        }

        // ensure stage kt+1 resident before next iteration
        if (kt + 1 < KT) {
            if (kt + 2 < KT) cp_wait<1>(); else cp_wait<0>();
            __syncthreads();
        }
    }

    // epilogue: scale + bias, round through fp16, f32 out
    const int gi = lane >> 2;
    const int tl = lane & 3;
#pragma unroll
    for (int ni = 0; ni < 8; ni++) {
        const int n = n0 + wn * 64 + ni * 8 + tl * 2;
        const float s0 = __ldg(scale + n), s1 = __ldg(scale + n + 1);
        const float z0 = __ldg(bias + n),  z1 = __ldg(bias + n + 1);
#pragma unroll
        for (int mi = 0; mi < 2; mi++) {
            const size_t r0 = (size_t)(m0 + wm * 32 + mi * 16 + gi);
            *(float2*)(out + r0 * N + n) =
                make_float2(rf16(acc[mi][ni][0] * s0 + z0), rf16(acc[mi][ni][1] * s1 + z1));
            *(float2*)(out + (r0 + 8) * N + n) =
                make_float2(rf16(acc[mi][ni][2] * s0 + z0), rf16(acc[mi][ni][3] * s1 + z1));
        }
    }
}

struct ForceLoad {
    ForceLoad() {
        cudaFuncAttributes a;
        cudaFuncGetAttributes(&a, (const void*)cvt_x);
        cudaFuncGetAttributes(&a, (const void*)cvt_w);
        cudaFuncGetAttributes(&a, (const void*)gemm_kernel);
        cudaFuncSetAttribute((const void*)gemm_kernel,
                             cudaFuncAttributeMaxDynamicSharedMemorySize, SMEM_TOTAL);
    }
};
ForceLoad g_forceload;

} // namespace

extern "C" void kernel_launch(void* const* d_in, const int* in_sizes, int n_in,
                              void* d_out, int out_size) {
    const float* X     = (const float*)d_in[0];
    const int*   W     = (const int*)d_in[1];
    const float* scale = (const float*)d_in[2];
    const float* bias  = (const float*)d_in[3];
    float* out = (float*)d_out;

    const int n0 = in_sizes[0];
    const int n1 = in_sizes[1];
    const int N  = in_sizes[2];            // 11008
    const int K  = n1 / N;                 // 4096
    const int M  = n0 / K;                 // 8192

    cvt_x<<<(n0 / 8 + 255) / 256, 256>>>(X, n0 / 8);
    cvt_w<<<(n1 / 8 + 255) / 256, 256>>>(W, n1 / 8);

    cudaFuncSetAttribute((const void*)gemm_kernel,
                         cudaFuncAttributeMaxDynamicSharedMemorySize, SMEM_TOTAL);
    dim3 grid(N / BN, M / BM);             // 86 x 64
    gemm_kernel<<<grid, THREADS, SMEM_TOTAL>>>(scale, bias, out, M, N, K);
}

// round 14
// speedup vs baseline: 1.0895x; 1.0033x over previous
#include <cuda_runtime.h>
#include <cuda_fp16.h>
#include <cstdint>
#include <cstddef>

// W8A16 GEMM, legacy-HMMA path (harness targets plain sm_103: tcgen05 unavailable).
// Contract (confirmed R4): X f32[M,K] (fp16-valued), W int32[N,K] (int8-valued),
// scale/bias f32[N], out f32[M,N] (fp16-rounded values).
// R14 = R7 (best: 1594us, untouched mainloop) + GROUP_N=16 rasterization with
// n-tile fastest inside the group: consecutive CTAs still share one A slab
// (R7's hot-A property preserved) while each wave's W working set shrinks to
// ~16MB (L2-resident; W fetched from DRAM once per group instead of ~18x).
// 128x128 CTA, BK=64, 8 warps (32x64 warp tiles), 3-stage cp.async ring
// (wait_group 1), SW128 smem, ldmatrix + mma.sync, 2 CTAs/SM.

namespace {

constexpr int MM = 8192, KK = 4096, NN = 11008;
constexpr int BM = 128, BN = 128, BK = 64;
constexpr int THREADS = 256;
constexpr int STAGES = 3;
constexpr int GROUP_N = 16;        // n-tiles per raster group
constexpr int ASTAGE = BM * 128;   // 16 KB
constexpr int BSTAGE = BN * 128;   // 16 KB
constexpr int SMEM_TOTAL = STAGES * (ASTAGE + BSTAGE);  // 96 KB

__device__ __align__(256) __half g_X16[(size_t)MM * KK];   // 64 MB
__device__ __align__(256) __half g_W16[(size_t)NN * KK];   // 90 MB

// ---------------- converters ----------------
__global__ void __launch_bounds__(256) cvt_x(const float* __restrict__ x, int total8) {
    int t = blockIdx.x * blockDim.x + threadIdx.x;
    if (t >= total8) return;
    size_t base = (size_t)t * 8;
    const float4* p = (const float4*)(x + base);
    float4 a = p[0], b = p[1];
    __half2 h0 = __floats2half2_rn(a.x, a.y), h1 = __floats2half2_rn(a.z, a.w);
    __half2 h2 = __floats2half2_rn(b.x, b.y), h3 = __floats2half2_rn(b.z, b.w);
    uint4 o;
    o.x = *(uint32_t*)&h0; o.y = *(uint32_t*)&h1;
    o.z = *(uint32_t*)&h2; o.w = *(uint32_t*)&h3;
    *(uint4*)(g_X16 + base) = o;
}

__global__ void __launch_bounds__(256) cvt_w(const int* __restrict__ w, int total8) {
    int t = blockIdx.x * blockDim.x + threadIdx.x;
    if (t >= total8) return;
    size_t base = (size_t)t * 8;
    const int4* p = (const int4*)(w + base);
    int4 a = p[0], b = p[1];
    __half h[8];
    h[0] = __int2half_rn(a.x); h[1] = __int2half_rn(a.y);
    h[2] = __int2half_rn(a.z); h[3] = __int2half_rn(a.w);
    h[4] = __int2half_rn(b.x); h[5] = __int2half_rn(b.y);
    h[6] = __int2half_rn(b.z); h[7] = __int2half_rn(b.w);
    uint4 o;
    o.x = *(uint32_t*)&h[0]; o.y = *(uint32_t*)&h[2];
    o.z = *(uint32_t*)&h[4]; o.w = *(uint32_t*)&h[6];
    *(uint4*)(g_W16 + base) = o;
}

// ---------------- helpers ----------------
__device__ __forceinline__ uint32_t swz(uint32_t x) { return x ^ ((x >> 3) & 0x70); }

__device__ __forceinline__ void cp_async16(uint32_t dst, const void* src) {
    asm volatile("cp.async.cg.shared.global [%0], [%1], 16;\n" :: "r"(dst), "l"(src));
}
__device__ __forceinline__ void cp_commit() { asm volatile("cp.async.commit_group;\n"); }
template <int N>
__device__ __forceinline__ void cp_wait() {
    asm volatile("cp.async.wait_group %0;\n" :: "n"(N) : "memory");
}

__device__ __forceinline__ void ldsm4(uint32_t r[4], uint32_t addr) {
    asm volatile("ldmatrix.sync.aligned.m8n8.x4.shared.b16 {%0,%1,%2,%3}, [%4];\n"
                 : "=r"(r[0]), "=r"(r[1]), "=r"(r[2]), "=r"(r[3]) : "r"(addr));
}

__device__ __forceinline__ void mma16816(float c[4], const uint32_t a[4],
                                         uint32_t b0, uint32_t b1) {
    asm volatile("mma.sync.aligned.m16n8k16.row.col.f32.f16.f16.f32 "
                 "{%0,%1,%2,%3}, {%4,%5,%6,%7}, {%8,%9}, {%0,%1,%2,%3};\n"
                 : "+f"(c[0]), "+f"(c[1]), "+f"(c[2]), "+f"(c[3])
                 : "r"(a[0]), "r"(a[1]), "r"(a[2]), "r"(a[3]), "r"(b0), "r"(b1));
}

__device__ __forceinline__ float rf16(float v) {
    return __half2float(__float2half_rn(v));
}

// ---------------- GEMM ----------------
__global__ void __launch_bounds__(THREADS, 2)
gemm_kernel(const float* __restrict__ scale, const float* __restrict__ bias,
            float* __restrict__ out, int M, int N, int K)
{
    extern __shared__ __align__(1024) char smem[];
    const uint32_t sA = (uint32_t)__cvta_generic_to_shared(smem);
    const uint32_t sB = sA + STAGES * ASTAGE;

    const int tid  = threadIdx.x;
    const int lane = tid & 31;
    const int warp = tid >> 5;
    const int wm = warp & 3;   // 4 warp rows x 32 M
    const int wn = warp >> 2;  // 2 warp cols x 64 N

    // Grouped raster, n-tile fastest inside a GROUP_N-wide group:
    //   - 16 consecutive CTAs share m0 (A slab stays L2-hot, as in R7)
    //   - a wave touches only GROUP_N W slabs (~16MB, L2-resident)
    // Remainder-correct because all groups before the last are full.
    {
    }
    const int num_m = gridDim.y;                    // 64
    const int num_n = gridDim.x;                    // 86
    const int pid   = blockIdx.y * num_n + blockIdx.x;
    const int per_g = GROUP_N * num_m;              // CTAs per full group
    const int gid   = pid / per_g;
    const int first_n = gid * GROUP_N;
    const int gsz   = (num_n - first_n) < GROUP_N ? (num_n - first_n) : GROUP_N;
    const int rem   = pid - gid * per_g;
    const int mt    = rem / gsz;
    const int nt    = first_n + (rem - mt * gsz);
    const int m0 = mt * BM;
    const int n0 = nt * BN;
    const int KT = K / BK;

    // staging: 1024 x 16B chunks per operand stage, 4 per thread
    uint32_t a_st[4]; const __half* a_g[4]; const __half* b_g[4];
#pragma unroll
    for (int i = 0; i < 4; i++) {
        int chunk = tid + i * THREADS;
        int row = chunk >> 3, c = chunk & 7;
        a_st[i] = swz((uint32_t)(row * 128 + c * 16));
        a_g[i]  = g_X16 + (size_t)(m0 + row) * K + c * 8;
        b_g[i]  = g_W16 + (size_t)(n0 + row) * K + c * 8;
    }

    // ldmatrix base offsets (swizzle xor is row-only -> constant per thread)
    const uint32_t a_off0 = (uint32_t)((wm * 32 + (lane & 15)) * 128 + (lane >> 4) * 16);
    const uint32_t axor   = (a_off0 >> 3) & 0x70;
    const uint32_t b_off0 = (uint32_t)((wn * 64 + ((lane >> 4) & 1) * 8 + (lane & 7)) * 128
                                       + ((lane >> 3) & 1) * 16);
    const uint32_t bxor   = (b_off0 >> 3) & 0x70;

    float acc[2][8][4];
#pragma unroll
    for (int mi = 0; mi < 2; mi++)
#pragma unroll
        for (int ni = 0; ni < 8; ni++)
#pragma unroll
            for (int e = 0; e < 4; e++) acc[mi][ni][e] = 0.f;

    // prologue: stages 0 and 1
#pragma unroll
    for (int s = 0; s < 2; s++) {
        const size_t ko = (size_t)s * BK;
#pragma unroll
        for (int i = 0; i < 4; i++) cp_async16(sA + s * ASTAGE + a_st[i], a_g[i] + ko);
#pragma unroll
        for (int i = 0; i < 4; i++) cp_async16(sB + s * BSTAGE + a_st[i], b_g[i] + ko);
        cp_commit();
    }
    cp_wait<1>();          // stage 0 resident
    __syncthreads();

    for (int kt = 0; kt < KT; ++kt) {
        // issue loads for kt+2 into the buffer freed at the end of kt-1
        if (kt + 2 < KT) {
            const int s = (kt + 2) % STAGES;
            const size_t ko = (size_t)(kt + 2) * BK;
#pragma unroll
            for (int i = 0; i < 4; i++) cp_async16(sA + s * ASTAGE + a_st[i], a_g[i] + ko);
#pragma unroll
            for (int i = 0; i < 4; i++) cp_async16(sB + s * BSTAGE + a_st[i], b_g[i] + ko);
            cp_commit();
        }

        // compute stage kt
        const uint32_t Abase = sA + (kt % STAGES) * ASTAGE;
        const uint32_t Bbase = sB + (kt % STAGES) * BSTAGE;
#pragma unroll
        for (int ks = 0; ks < 4; ++ks) {
            uint32_t a[2][4];
#pragma unroll
            for (int mi = 0; mi < 2; mi++)
                ldsm4(a[mi], Abase + ((a_off0 + mi * 2048 + ks * 32) ^ axor));
#pragma unroll
            for (int np = 0; np < 4; np++) {
                uint32_t b[4];
                ldsm4(b, Bbase + ((b_off0 + np * 2048 + ks * 32) ^ bxor));
#pragma unroll
                for (int mi = 0; mi < 2; mi++) {
                    mma16816(acc[mi][2 * np],     a[mi], b[0], b[1]);
                    mma16816(acc[mi][2 * np + 1], a[mi], b[2], b[3]);
                }
            }
        }

        // ensure stage kt+1 resident before next iteration
        if (kt + 1 < KT) {
            if (kt + 2 < KT) cp_wait<1>(); else cp_wait<0>();
            __syncthreads();
        }
    }

    // epilogue: scale + bias, round through fp16, f32 out
    const int gi = lane >> 2;
    const int tl = lane & 3;
#pragma unroll
    for (int ni = 0; ni < 8; ni++) {
        const int n = n0 + wn * 64 + ni * 8 + tl * 2;
        const float s0 = __ldg(scale + n), s1 = __ldg(scale + n + 1);
        const float z0 = __ldg(bias + n),  z1 = __ldg(bias + n + 1);
#pragma unroll
        for (int mi = 0; mi < 2; mi++) {
            const size_t r0 = (size_t)(m0 + wm * 32 + mi * 16 + gi);
            *(float2*)(out + r0 * N + n) =
                make_float2(rf16(acc[mi][ni][0] * s0 + z0), rf16(acc[mi][ni][1] * s1 + z1));
            *(float2*)(out + (r0 + 8) * N + n) =
                make_float2(rf16(acc[mi][ni][2] * s0 + z0), rf16(acc[mi][ni][3] * s1 + z1));
        }
    }
}

struct ForceLoad {
    ForceLoad() {
        cudaFuncAttributes a;
        cudaFuncGetAttributes(&a, (const void*)cvt_x);
        cudaFuncGetAttributes(&a, (const void*)cvt_w);
        cudaFuncGetAttributes(&a, (const void*)gemm_kernel);
        cudaFuncSetAttribute((const void*)gemm_kernel,
                             cudaFuncAttributeMaxDynamicSharedMemorySize, SMEM_TOTAL);
    }
};
ForceLoad g_forceload;

} // namespace

extern "C" void kernel_launch(void* const* d_in, const int* in_sizes, int n_in,
                              void* d_out, int out_size) {
    const float* X     = (const float*)d_in[0];
    const int*   W     = (const int*)d_in[1];
    const float* scale = (const float*)d_in[2];
    const float* bias  = (const float*)d_in[3];
    float* out = (float*)d_out;

    const int n0 = in_sizes[0];
    const int n1 = in_sizes[1];
    const int N  = in_sizes[2];            // 11008
    const int K  = n1 / N;                 // 4096
    const int M  = n0 / K;                 // 8192

    cvt_x<<<(n0 / 8 + 255) / 256, 256>>>(X, n0 / 8);
    cvt_w<<<(n1 / 8 + 255) / 256, 256>>>(W, n1 / 8);

    cudaFuncSetAttribute((const void*)gemm_kernel,
                         cudaFuncAttributeMaxDynamicSharedMemorySize, SMEM_TOTAL);
    dim3 grid(N / BN, M / BM);             // 86 x 64
    gemm_kernel<<<grid, THREADS, SMEM_TOTAL>>>(scale, bias, out, M, N, K);
}

// round 15
// speedup vs baseline: 1.1587x; 1.0635x over previous
#include <cuda_runtime.h>
#include <cuda_fp16.h>
#include <cstdint>
#include <cstddef>

// W8A16 GEMM, legacy-HMMA path (harness targets plain sm_103: tcgen05 unavailable).
// Contract (confirmed R4): X f32[M,K] (fp16-valued), W int32[N,K] (int8-valued),
// scale/bias f32[N], out f32[M,N] (fp16-rounded values).
// R15 = R7 (best: 1594us) restored bit-for-bit, with the two converter
// kernels fused into ONE launch (combined index space: X chunks then W
// chunks) to remove one launch + wave-drain tail. GEMM untouched:
// 128x128 CTA, BK=64, 8 warps (32x64 warp tiles), 3-stage cp.async ring
// (wait_group 1), SW128 smem, ldmatrix + mma.sync, 2 CTAs/SM, default raster.

namespace {

constexpr int MM = 8192, KK = 4096, NN = 11008;
constexpr int BM = 128, BN = 128, BK = 64;
constexpr int THREADS = 256;
constexpr int STAGES = 3;
constexpr int ASTAGE = BM * 128;   // 16 KB
constexpr int BSTAGE = BN * 128;   // 16 KB
constexpr int SMEM_TOTAL = STAGES * (ASTAGE + BSTAGE);  // 96 KB

__device__ __align__(256) __half g_X16[(size_t)MM * KK];   // 64 MB
__device__ __align__(256) __half g_W16[(size_t)NN * KK];   // 90 MB

// ---------------- fused converter ----------------
// Chunk t < XCH: convert 8 f32 -> 8 fp16 of X. Chunk t >= XCH: 8 int32 -> fp16 of W.
constexpr int XCH = MM * KK / 8;       // 4,194,304 X chunks
constexpr int WCH = NN * KK / 8;       // 5,636,096 W chunks

__global__ void __launch_bounds__(256) cvt_xw(const float* __restrict__ x,
                                              const int* __restrict__ w) {
    int t = blockIdx.x * blockDim.x + threadIdx.x;
    if (t < XCH) {
        size_t base = (size_t)t * 8;
        const float4* p = (const float4*)(x + base);
        float4 a = p[0], b = p[1];
        __half2 h0 = __floats2half2_rn(a.x, a.y), h1 = __floats2half2_rn(a.z, a.w);
        __half2 h2 = __floats2half2_rn(b.x, b.y), h3 = __floats2half2_rn(b.z, b.w);
        uint4 o;
        o.x = *(uint32_t*)&h0; o.y = *(uint32_t*)&h1;
        o.z = *(uint32_t*)&h2; o.w = *(uint32_t*)&h3;
        *(uint4*)(g_X16 + base) = o;
    } else if (t < XCH + WCH) {
        size_t base = (size_t)(t - XCH) * 8;
        const int4* p = (const int4*)(w + base);
        int4 a = p[0], b = p[1];
        __half h[8];
        h[0] = __int2half_rn(a.x); h[1] = __int2half_rn(a.y);
        h[2] = __int2half_rn(a.z); h[3] = __int2half_rn(a.w);
        h[4] = __int2half_rn(b.x); h[5] = __int2half_rn(b.y);
        h[6] = __int2half_rn(b.z); h[7] = __int2half_rn(b.w);
        uint4 o;
        o.x = *(uint32_t*)&h[0]; o.y = *(uint32_t*)&h[2];
        o.z = *(uint32_t*)&h[4]; o.w = *(uint32_t*)&h[6];
        *(uint4*)(g_W16 + base) = o;
    }
}

// ---------------- helpers ----------------
__device__ __forceinline__ uint32_t swz(uint32_t x) { return x ^ ((x >> 3) & 0x70); }

__device__ __forceinline__ void cp_async16(uint32_t dst, const void* src) {
    asm volatile("cp.async.cg.shared.global [%0], [%1], 16;\n" :: "r"(dst), "l"(src));
}
__device__ __forceinline__ void cp_commit() { asm volatile("cp.async.commit_group;\n"); }
template <int N>
__device__ __forceinline__ void cp_wait() {
    asm volatile("cp.async.wait_group %0;\n" :: "n"(N) : "memory");
}

__device__ __forceinline__ void ldsm4(uint32_t r[4], uint32_t addr) {
    asm volatile("ldmatrix.sync.aligned.m8n8.x4.shared.b16 {%0,%1,%2,%3}, [%4];\n"
                 : "=r"(r[0]), "=r"(r[1]), "=r"(r[2]), "=r"(r[3]) : "r"(addr));
}

__device__ __forceinline__ void mma16816(float c[4], const uint32_t a[4],
                                         uint32_t b0, uint32_t b1) {
    asm volatile("mma.sync.aligned.m16n8k16.row.col.f32.f16.f16.f32 "
                 "{%0,%1,%2,%3}, {%4,%5,%6,%7}, {%8,%9}, {%0,%1,%2,%3};\n"
                 : "+f"(c[0]), "+f"(c[1]), "+f"(c[2]), "+f"(c[3])
                 : "r"(a[0]), "r"(a[1]), "r"(a[2]), "r"(a[3]), "r"(b0), "r"(b1));
}

__device__ __forceinline__ float rf16(float v) {
    return __half2float(__float2half_rn(v));
}

// ---------------- GEMM (identical to R7) ----------------
__global__ void __launch_bounds__(THREADS, 2)
gemm_kernel(const float* __restrict__ scale, const float* __restrict__ bias,
            float* __restrict__ out, int M, int N, int K)
{
    extern __shared__ __align__(1024) char smem[];
    const uint32_t sA = (uint32_t)__cvta_generic_to_shared(smem);
    const uint32_t sB = sA + STAGES * ASTAGE;

    const int tid  = threadIdx.x;
    const int lane = tid & 31;
    const int warp = tid >> 5;
    const int wm = warp & 3;   // 4 warp rows x 32 M
    const int wn = warp >> 2;  // 2 warp cols x 64 N

    const int m0 = blockIdx.y * BM;
    const int n0 = blockIdx.x * BN;   // x = N: a wave shares the A slab, streams W
    const int KT = K / BK;

    // staging: 1024 x 16B chunks per operand stage, 4 per thread
    uint32_t a_st[4]; const __half* a_g[4]; const __half* b_g[4];
#pragma unroll
    for (int i = 0; i < 4; i++) {
        int chunk = tid + i * THREADS;
        int row = chunk >> 3, c = chunk & 7;
        a_st[i] = swz((uint32_t)(row * 128 + c * 16));
        a_g[i]  = g_X16 + (size_t)(m0 + row) * K + c * 8;
        b_g[i]  = g_W16 + (size_t)(n0 + row) * K + c * 8;
    }

    // ldmatrix base offsets (swizzle xor is row-only -> constant per thread)
    const uint32_t a_off0 = (uint32_t)((wm * 32 + (lane & 15)) * 128 + (lane >> 4) * 16);
    const uint32_t axor   = (a_off0 >> 3) & 0x70;
    const uint32_t b_off0 = (uint32_t)((wn * 64 + ((lane >> 4) & 1) * 8 + (lane & 7)) * 128
                                       + ((lane >> 3) & 1) * 16);
    const uint32_t bxor   = (b_off0 >> 3) & 0x70;

    float acc[2][8][4];
#pragma unroll
    for (int mi = 0; mi < 2; mi++)
#pragma unroll
        for (int ni = 0; ni < 8; ni++)
#pragma unroll
            for (int e = 0; e < 4; e++) acc[mi][ni][e] = 0.f;

    // prologue: stages 0 and 1
#pragma unroll
    for (int s = 0; s < 2; s++) {
        const size_t ko = (size_t)s * BK;
#pragma unroll
        for (int i = 0; i < 4; i++) cp_async16(sA + s * ASTAGE + a_st[i], a_g[i] + ko);
#pragma unroll
        for (int i = 0; i < 4; i++) cp_async16(sB + s * BSTAGE + a_st[i], b_g[i] + ko);
        cp_commit();
    }
    cp_wait<1>();          // stage 0 resident
    __syncthreads();

    for (int kt = 0; kt < KT; ++kt) {
        // issue loads for kt+2 into the buffer freed at the end of kt-1
        if (kt + 2 < KT) {
            const int s = (kt + 2) % STAGES;
            const size_t ko = (size_t)(kt + 2) * BK;
#pragma unroll
            for (int i = 0; i < 4; i++) cp_async16(sA + s * ASTAGE + a_st[i], a_g[i] + ko);
#pragma unroll
            for (int i = 0; i < 4; i++) cp_async16(sB + s * BSTAGE + a_st[i], b_g[i] + ko);
            cp_commit();
        }

        // compute stage kt
        const uint32_t Abase = sA + (kt % STAGES) * ASTAGE;
        const uint32_t Bbase = sB + (kt % STAGES) * BSTAGE;
#pragma unroll
        for (int ks = 0; ks < 4; ++ks) {
            uint32_t a[2][4];
#pragma unroll
            for (int mi = 0; mi < 2; mi++)
                ldsm4(a[mi], Abase + ((a_off0 + mi * 2048 + ks * 32) ^ axor));
#pragma unroll
            for (int np = 0; np < 4; np++) {
                uint32_t b[4];
                ldsm4(b, Bbase + ((b_off0 + np * 2048 + ks * 32) ^ bxor));
#pragma unroll
                for (int mi = 0; mi < 2; mi++) {
                    mma16816(acc[mi][2 * np],     a[mi], b[0], b[1]);
                    mma16816(acc[mi][2 * np + 1], a[mi], b[2], b[3]);
                }
            }
        }

        // ensure stage kt+1 resident before next iteration
        if (kt + 1 < KT) {
            if (kt + 2 < KT) cp_wait<1>(); else cp_wait<0>();
            __syncthreads();
        }
    }

    // epilogue: scale + bias, round through fp16, f32 out
    const int gi = lane >> 2;
    const int tl = lane & 3;
#pragma unroll
    for (int ni = 0; ni < 8; ni++) {
        const int n = n0 + wn * 64 + ni * 8 + tl * 2;
        const float s0 = __ldg(scale + n), s1 = __ldg(scale + n + 1);
        const float z0 = __ldg(bias + n),  z1 = __ldg(bias + n + 1);
#pragma unroll
        for (int mi = 0; mi < 2; mi++) {
            const size_t r0 = (size_t)(m0 + wm * 32 + mi * 16 + gi);
            *(float2*)(out + r0 * N + n) =
                make_float2(rf16(acc[mi][ni][0] * s0 + z0), rf16(acc[mi][ni][1] * s1 + z1));
            *(float2*)(out + (r0 + 8) * N + n) =
                make_float2(rf16(acc[mi][ni][2] * s0 + z0), rf16(acc[mi][ni][3] * s1 + z1));
        }
    }
}

struct ForceLoad {
    ForceLoad() {
        cudaFuncAttributes a;
        cudaFuncGetAttributes(&a, (const void*)cvt_xw);
        cudaFuncGetAttributes(&a, (const void*)gemm_kernel);
        cudaFuncSetAttribute((const void*)gemm_kernel,
                             cudaFuncAttributeMaxDynamicSharedMemorySize, SMEM_TOTAL);
    }
};
ForceLoad g_forceload;

} // namespace

extern "C" void kernel_launch(void* const* d_in, const int* in_sizes, int n_in,
                              void* d_out, int out_size) {
    const float* X     = (const float*)d_in[0];
    const int*   W     = (const int*)d_in[1];
    const float* scale = (const float*)d_in[2];
    const float* bias  = (const float*)d_in[3];
    float* out = (float*)d_out;

    const int n0 = in_sizes[0];
    const int n1 = in_sizes[1];
    const int N  = in_sizes[2];            // 11008
    const int K  = n1 / N;                 // 4096
    const int M  = n0 / K;                 // 8192

    const int total = XCH + WCH;
    cvt_xw<<<(total + 255) / 256, 256>>>(X, W);

    cudaFuncSetAttribute((const void*)gemm_kernel,
                         cudaFuncAttributeMaxDynamicSharedMemorySize, SMEM_TOTAL);
    dim3 grid(N / BN, M / BM);             // 86 x 64
    gemm_kernel<<<grid, THREADS, SMEM_TOTAL>>>(scale, bias, out, M, N, K);
}